// round 10
// baseline (speedup 1.0000x reference)
#include <cuda_runtime.h>

// Problem constants
#define BB    64
#define CC    128
#define TT    500
#define NRES  2048
#define NCLS  10
#define DECAY 0.9f
#define VTH   1.0f

// Eigen gebp kc blocking, SINGLE-THREAD branch with even-redistribution:
// max_kc=248, k=2048 -> kc = 248 - 8*floor(183/72) = 232.
#define KCHUNK 232

// Tiling
#define JTILE 16                    // neurons per reservoir block
#define NRES_BLOCKS (NRES / JTILE)  // 128
#define CLF_BLOCKS  3
#define THREADS 256
#define KC 64                       // k-chunk staged per iteration
#define WPAD 2052                   // padded W row in floats
#define SPAD 68                     // padded s row in floats

#define SMEM_FLOATS (JTILE * WPAD + BB * SPAD)
#define SMEM_BYTES  (SMEM_FLOATS * 4)

// Persistent device scratch
__device__ float g_FF[(size_t)TT * BB * NRES]; // precomputed feedforward
__device__ float g_vr[BB * NRES];
__device__ float g_vc[BB * NCLS];
__device__ float g_s[2][BB * NRES];            // double-buffered spikes
__device__ float g_WinT[CC * NRES];            // W_in transposed [c][j]

// ---------------------------------------------------------------------------
__global__ void zero_init_kernel(float* d_out, int out_size) {
    int i = blockIdx.x * blockDim.x + threadIdx.x;
    if (i < BB * NRES)      g_vr[i] = 0.0f;
    if (i < BB * NCLS)      g_vc[i] = 0.0f;
    if (i < 2 * BB * NRES)  (&g_s[0][0])[i] = 0.0f;
    if (i < out_size)       d_out[i] = 0.0f;
}

// ---------------------------------------------------------------------------
__global__ void transpose_win_kernel(const float* __restrict__ Win) {
    int i = blockIdx.x * blockDim.x + threadIdx.x;  // over C*NRES
    if (i < CC * NRES) {
        int c = i / NRES;
        int j = i % NRES;
        g_WinT[i] = Win[j * CC + c];
    }
}

// ---------------------------------------------------------------------------
// FF[t][b][j] = sum_c x[b][c][t] * W_in[j][c].
// k = 128 < KCHUNK -> single chunk: strict serial ascending fp32 FMA.
__global__ void __launch_bounds__(256) ff_kernel(const float* __restrict__ x) {
    int t = blockIdx.x / BB;
    int b = blockIdx.x % BB;
    __shared__ float xs[CC];
    int tid = threadIdx.x;
    if (tid < CC) xs[tid] = x[(size_t)b * CC * TT + tid * TT + t];
    __syncthreads();

    const float4* W4 = (const float4*)g_WinT;   // [c][NRES/4]
    float a0 = 0.f, a1 = 0.f, a2 = 0.f, a3 = 0.f;
    float a4 = 0.f, a5 = 0.f, a6 = 0.f, a7 = 0.f;
    #pragma unroll 4
    for (int c = 0; c < CC; c++) {          // ascending c
        float xv = xs[c];
        float4 w0 = W4[c * (NRES / 4) + tid];
        float4 w1 = W4[c * (NRES / 4) + tid + 256];
        a0 = fmaf(xv, w0.x, a0); a1 = fmaf(xv, w0.y, a1);
        a2 = fmaf(xv, w0.z, a2); a3 = fmaf(xv, w0.w, a3);
        a4 = fmaf(xv, w1.x, a4); a5 = fmaf(xv, w1.y, a5);
        a6 = fmaf(xv, w1.z, a6); a7 = fmaf(xv, w1.w, a7);
    }
    float4* out = (float4*)(g_FF + (size_t)t * BB * NRES + (size_t)b * NRES);
    out[tid]       = make_float4(a0, a1, a2, a3);
    out[tid + 256] = make_float4(a4, a5, a6, a7);
}

// ---------------------------------------------------------------------------
// One launch per time step. Blocks [0,128): reservoir update for `step`.
// Blocks [128,131): classifier for s_{step-1}.
// Reservoir dot: Eigen gebp chunked accumulation (KCHUNK=232 flush-adds).
// Classifier dot: pure serial ascending-k FMA (bit-equivalent per R8).
// State updates: UNCONTRACTED mul/add.
__global__ void __launch_bounds__(THREADS, 1)
step_kernel(int step,
            const float* __restrict__ Wres,
            const float* __restrict__ Wclf,
            float* __restrict__ d_out) {
    extern __shared__ float sm[];
    int tid = threadIdx.x;
    int bid = blockIdx.x;
    int rb = (step + 1) & 1;  // buffer holding s_{step-1}
    int wb = step & 1;        // buffer receiving s_step

    if (bid < NRES_BLOCKS) {
        if (step >= TT) return;
        float* Wsm = sm;                     // [JTILE][WPAD]
        float* Ssm = sm + JTILE * WPAD;      // [BB][SPAD]
        int j0 = bid * JTILE;

        // Stage this block's 16 W_res rows into smem.
        {
            const float4* Wg = (const float4*)(Wres + (size_t)j0 * NRES);
            float4* Wsm4 = (float4*)Wsm;
            #pragma unroll
            for (int u = 0; u < (JTILE * NRES / 4) / THREADS; u++) {
                int fi  = tid + u * THREADS;
                int row = fi / (NRES / 4);
                int c4  = fi % (NRES / 4);
                Wsm4[row * (WPAD / 4) + c4] = Wg[row * (NRES / 4) + c4];
            }
        }

        int b  = tid >> 2;        // 0..63
        int jq = tid & 3;         // 0..3
        int jb = jq * 4;          // local neuron base
        float acc0 = 0.f, acc1 = 0.f, acc2 = 0.f, acc3 = 0.f;
        float p0 = 0.f, p1 = 0.f, p2 = 0.f, p3 = 0.f;
        int nextb = KCHUNK;       // next chunk boundary (multiple of 8)

        const float4* sglob = (const float4*)(&g_s[rb][0]);
        const float4* Wsm4  = (const float4*)Wsm;

        for (int kc0 = 0; kc0 < NRES; kc0 += KC) {   // ascending staging
            __syncthreads();
            // stage s[0:64][kc0:kc0+64] -> Ssm
            {
                float4* Ssm4 = (float4*)Ssm;
                #pragma unroll
                for (int u = 0; u < 4; u++) {
                    int fi  = tid + u * THREADS;
                    int row = fi / (KC / 4);
                    int c4  = fi % (KC / 4);
                    Ssm4[row * (SPAD / 4) + c4] =
                        sglob[row * (NRES / 4) + (kc0 / 4) + c4];
                }
            }
            __syncthreads();

            const float4* Sr = (const float4*)(Ssm + b * SPAD);
            #pragma unroll
            for (int k4 = 0; k4 < KC / 4; k4++) {  // ascending quads
                int kglob = kc0 + k4 * 4;
                if (kglob == nextb) {              // chunk boundary: flush
                    acc0 = __fadd_rn(acc0, p0); p0 = 0.f;
                    acc1 = __fadd_rn(acc1, p1); p1 = 0.f;
                    acc2 = __fadd_rn(acc2, p2); p2 = 0.f;
                    acc3 = __fadd_rn(acc3, p3); p3 = 0.f;
                    nextb += KCHUNK;
                }
                float4 sv = Sr[k4];
                int ka = (kc0 >> 2) + k4;
                float4 w0 = Wsm4[(jb + 0) * (WPAD / 4) + ka];
                float4 w1 = Wsm4[(jb + 1) * (WPAD / 4) + ka];
                float4 w2 = Wsm4[(jb + 2) * (WPAD / 4) + ka];
                float4 w3 = Wsm4[(jb + 3) * (WPAD / 4) + ka];
                // ascending within quad
                p0 = fmaf(sv.x, w0.x, p0);
                p0 = fmaf(sv.y, w0.y, p0);
                p0 = fmaf(sv.z, w0.z, p0);
                p0 = fmaf(sv.w, w0.w, p0);
                p1 = fmaf(sv.x, w1.x, p1);
                p1 = fmaf(sv.y, w1.y, p1);
                p1 = fmaf(sv.z, w1.z, p1);
                p1 = fmaf(sv.w, w1.w, p1);
                p2 = fmaf(sv.x, w2.x, p2);
                p2 = fmaf(sv.y, w2.y, p2);
                p2 = fmaf(sv.z, w2.z, p2);
                p2 = fmaf(sv.w, w2.w, p2);
                p3 = fmaf(sv.x, w3.x, p3);
                p3 = fmaf(sv.y, w3.y, p3);
                p3 = fmaf(sv.z, w3.z, p3);
                p3 = fmaf(sv.w, w3.w, p3);
            }
        }
        // final chunk flush
        acc0 = __fadd_rn(acc0, p0);
        acc1 = __fadd_rn(acc1, p1);
        acc2 = __fadd_rn(acc2, p2);
        acc3 = __fadd_rn(acc3, p3);

        // Epilogue: I = ff + rec (single fp32 RN add), v = 0.9*v + I,
        // UNCONTRACTED (separate mul/add).
        int j = j0 + jb;
        size_t off = (size_t)b * NRES + j;
        float4 ff = *(const float4*)(g_FF + (size_t)step * BB * NRES + off);
        float4 v  = *(const float4*)(g_vr + off);
        float4 sp;
        float I0 = __fadd_rn(ff.x, acc0);
        float I1 = __fadd_rn(ff.y, acc1);
        float I2 = __fadd_rn(ff.z, acc2);
        float I3 = __fadd_rn(ff.w, acc3);
        v.x = __fadd_rn(__fmul_rn(DECAY, v.x), I0);
        v.y = __fadd_rn(__fmul_rn(DECAY, v.y), I1);
        v.z = __fadd_rn(__fmul_rn(DECAY, v.z), I2);
        v.w = __fadd_rn(__fmul_rn(DECAY, v.w), I3);
        sp.x = (v.x >= VTH) ? 1.0f : 0.0f;  if (v.x >= VTH) v.x = 0.0f;
        sp.y = (v.y >= VTH) ? 1.0f : 0.0f;  if (v.y >= VTH) v.y = 0.0f;
        sp.z = (v.z >= VTH) ? 1.0f : 0.0f;  if (v.z >= VTH) v.z = 0.0f;
        sp.w = (v.w >= VTH) ? 1.0f : 0.0f;  if (v.w >= VTH) v.w = 0.0f;
        *(float4*)(g_vr + off)        = v;
        *(float4*)(&g_s[wb][0] + off) = sp;

        float4* ac = (float4*)(d_out + NCLS * BB + off);
        float4 a = *ac;
        a.x += sp.x; a.y += sp.y; a.z += sp.z; a.w += sp.w;
        *ac = a;
    } else {
        // Classifier for s_{step-1}: pure serial ascending-k FMA.
        if (step == 0) return;
        int idx = (bid - NRES_BLOCKS) * THREADS + tid;
        if (idx >= BB * NCLS) return;
        int b   = idx / NCLS;
        int cls = idx % NCLS;
        const float4* sr = (const float4*)(&g_s[rb][0] + (size_t)b * NRES);
        const float4* wr = (const float4*)(Wclf + (size_t)cls * NRES);
        float acc = 0.f;
        #pragma unroll 8
        for (int k4 = 0; k4 < NRES / 4; k4++) {
            float4 s4 = sr[k4];
            float4 w4 = wr[k4];
            acc = fmaf(s4.x, w4.x, acc);
            acc = fmaf(s4.y, w4.y, acc);
            acc = fmaf(s4.z, w4.z, acc);
            acc = fmaf(s4.w, w4.w, acc);
        }
        float vc = g_vc[idx];
        vc = __fadd_rn(__fmul_rn(DECAY, vc), acc);
        if (vc >= VTH) {
            d_out[idx] += 1.0f;
            vc = 0.0f;
        }
        g_vc[idx] = vc;
    }
}

// ---------------------------------------------------------------------------
extern "C" void kernel_launch(void* const* d_in, const int* in_sizes, int n_in,
                              void* d_out, int out_size) {
    const float* x    = (const float*)d_in[0];  // (64,128,500)
    const float* Win  = (const float*)d_in[1];  // (2048,128)
    const float* Wres = (const float*)d_in[2];  // (2048,2048)
    const float* Wclf = (const float*)d_in[3];  // (10,2048)
    float* out = (float*)d_out;                 // [640 counts | 131072 accum]

    cudaFuncSetAttribute(step_kernel,
                         cudaFuncAttributeMaxDynamicSharedMemorySize, SMEM_BYTES);

    {
        int n = 2 * BB * NRES;
        if (out_size > n) n = out_size;
        int grid = (n + THREADS - 1) / THREADS;
        zero_init_kernel<<<grid, THREADS>>>(out, out_size);
    }

    transpose_win_kernel<<<(CC * NRES + THREADS - 1) / THREADS, THREADS>>>(Win);

    // Precompute all feedforward drives FF[t][b][j]
    ff_kernel<<<TT * BB, 256>>>(x);

    // Sequential LIF steps; step==TT runs only the final classifier.
    for (int t = 0; t <= TT; t++) {
        step_kernel<<<NRES_BLOCKS + CLF_BLOCKS, THREADS, SMEM_BYTES>>>(
            t, Wres, Wclf, out);
    }
}

// round 11
// speedup vs baseline: 1.7188x; 1.7188x over previous
#include <cuda_runtime.h>

// Problem constants
#define BB    64
#define CC    128
#define TT    500
#define NRES  2048
#define NCLS  10
#define DECAY 0.9f
#define VTH   1.0f

// Eigen gebp single-thread kc (CONFIRMED bit-exact in R10). Do not change.
#define KCHUNK 232

#define NRES_BLOCKS 128     // 16 neurons per reservoir block
#define CLF_BLOCKS  3
#define THREADS 256
#define JPAD 20             // smem row stride in floats for 16-j W rows

#define SMEM_BYTES (NRES * JPAD * 4 + 64 * 4)   // W tile + 64 mask words

// Persistent device scratch
__device__ float    g_FF[(size_t)TT * BB * NRES]; // precomputed feedforward
__device__ float    g_vr[BB * NRES];
__device__ float    g_vc[BB * NCLS];
__device__ unsigned g_mask[2][BB * NRES_BLOCKS];  // spike bitmasks [buf][b*128+slice]
__device__ float    g_WinT[CC * NRES];            // W_in transposed [c][j]
__device__ float    g_Wslice[(size_t)NRES_BLOCKS * NRES * 16]; // [slice][k][jl]

// ---------------------------------------------------------------------------
__global__ void zero_init_kernel(float* d_out, int out_size) {
    int i = blockIdx.x * blockDim.x + threadIdx.x;
    if (i < BB * NRES)                  g_vr[i] = 0.0f;
    if (i < BB * NCLS)                  g_vc[i] = 0.0f;
    if (i < 2 * BB * NRES_BLOCKS)       (&g_mask[0][0])[i] = 0u;
    if (i < out_size)                   d_out[i] = 0.0f;
}

// ---------------------------------------------------------------------------
__global__ void transpose_win_kernel(const float* __restrict__ Win) {
    int i = blockIdx.x * blockDim.x + threadIdx.x;
    if (i < CC * NRES) {
        int c = i / NRES;
        int j = i % NRES;
        g_WinT[i] = Win[j * CC + c];
    }
}

// ---------------------------------------------------------------------------
// g_Wslice[j>>4][k][j&15] = Wres[j][k], tiled 32x32 transpose.
__global__ void build_wslice_kernel(const float* __restrict__ Wres) {
    __shared__ float tile[32][33];
    int kBase = blockIdx.x * 32;
    int jBase = blockIdx.y * 32;
    int tx = threadIdx.x;        // 0..31
    int ty = threadIdx.y;        // 0..7
    for (int r = ty; r < 32; r += 8)
        tile[r][tx] = Wres[(size_t)(jBase + r) * NRES + kBase + tx];
    __syncthreads();
    for (int r = ty; r < 32; r += 8) {
        int k = kBase + r;
        int j = jBase + tx;
        g_Wslice[((size_t)(j >> 4) * NRES + k) * 16 + (j & 15)] = tile[tx][r];
    }
}

// ---------------------------------------------------------------------------
// FF[t][b][j] = sum_c x[b][c][t] * W_in[j][c].
// k=128 < KCHUNK -> single chunk: strict serial ascending fp32 FMA. (Frozen.)
__global__ void __launch_bounds__(256) ff_kernel(const float* __restrict__ x) {
    int t = blockIdx.x / BB;
    int b = blockIdx.x % BB;
    __shared__ float xs[CC];
    int tid = threadIdx.x;
    if (tid < CC) xs[tid] = x[(size_t)b * CC * TT + tid * TT + t];
    __syncthreads();

    const float4* W4 = (const float4*)g_WinT;
    float a0 = 0.f, a1 = 0.f, a2 = 0.f, a3 = 0.f;
    float a4 = 0.f, a5 = 0.f, a6 = 0.f, a7 = 0.f;
    #pragma unroll 4
    for (int c = 0; c < CC; c++) {
        float xv = xs[c];
        float4 w0 = W4[c * (NRES / 4) + tid];
        float4 w1 = W4[c * (NRES / 4) + tid + 256];
        a0 = fmaf(xv, w0.x, a0); a1 = fmaf(xv, w0.y, a1);
        a2 = fmaf(xv, w0.z, a2); a3 = fmaf(xv, w0.w, a3);
        a4 = fmaf(xv, w1.x, a4); a5 = fmaf(xv, w1.y, a5);
        a6 = fmaf(xv, w1.z, a6); a7 = fmaf(xv, w1.w, a7);
    }
    float4* out = (float4*)(g_FF + (size_t)t * BB * NRES + (size_t)b * NRES);
    out[tid]       = make_float4(a0, a1, a2, a3);
    out[tid + 256] = make_float4(a4, a5, a6, a7);
}

// ---------------------------------------------------------------------------
// Sparse step: spikes are 0/1, so skipping zeros and using FADD is BIT-EXACT
// vs the confirmed fmaf chain (fmaf(0,w,p)==p, fmaf(1,w,p)==RN(w+p)).
// Chunk flushes fire at crossed 232-boundaries; empty-chunk flushes are exact
// identities, so the collapsed flush sequence is bit-identical.
__global__ void __launch_bounds__(THREADS, 1)
step_kernel(int step,
            const float* __restrict__ Wclf,
            float* __restrict__ d_out) {
    extern __shared__ float sm[];
    unsigned* msk = (unsigned*)(sm + NRES * JPAD);
    int tid = threadIdx.x;
    int bid = blockIdx.x;
    int rb = (step + 1) & 1;  // masks of s_{step-1}
    int wb = step & 1;        // masks receiving s_step

    if (bid < NRES_BLOCKS) {
        if (step >= TT) return;
        if (tid < 64) msk[tid] = 0u;

        // Stage this block's W slice [2048 k][16 j] into padded smem [k][20].
        {
            const float4* src = (const float4*)(g_Wslice + (size_t)bid * NRES * 16);
            float4* dst = (float4*)sm;
            #pragma unroll
            for (int u = 0; u < 32; u++) {
                int f = tid + u * THREADS;   // float4 index 0..8191
                int k = f >> 2, q = f & 3;
                dst[k * (JPAD / 4) + q] = src[f];
            }
        }

        int b  = tid >> 2;
        int jq = tid & 3;
        int jb = jq * 4;
        size_t off = (size_t)b * NRES + bid * 16 + jb;
        // Issue long-latency loads before the sync.
        float4 ff = *(const float4*)(g_FF + (size_t)step * BB * NRES + off);
        float4 v  = *(const float4*)(g_vr + off);
        const unsigned* mrow = &g_mask[rb][b * NRES_BLOCKS];
        __syncthreads();

        float acc0 = 0.f, acc1 = 0.f, acc2 = 0.f, acc3 = 0.f;
        float p0 = 0.f, p1 = 0.f, p2 = 0.f, p3 = 0.f;
        int nextb = KCHUNK;

        for (int i = 0; i < NRES_BLOCKS; i++) {
            unsigned m = mrow[i];
            while (m) {
                unsigned t = m & (0u - m);       // lowest set bit
                int k = (i << 4) + __popc(t - 1u);
                m ^= t;
                while (k >= nextb) {             // crossed chunk boundaries
                    acc0 = __fadd_rn(acc0, p0); p0 = 0.f;
                    acc1 = __fadd_rn(acc1, p1); p1 = 0.f;
                    acc2 = __fadd_rn(acc2, p2); p2 = 0.f;
                    acc3 = __fadd_rn(acc3, p3); p3 = 0.f;
                    nextb += KCHUNK;
                }
                float4 w = *(const float4*)&sm[k * JPAD + jb];
                p0 = __fadd_rn(p0, w.x);
                p1 = __fadd_rn(p1, w.y);
                p2 = __fadd_rn(p2, w.z);
                p3 = __fadd_rn(p3, w.w);
            }
        }
        // Final flush (covers all remaining boundaries exactly).
        acc0 = __fadd_rn(acc0, p0);
        acc1 = __fadd_rn(acc1, p1);
        acc2 = __fadd_rn(acc2, p2);
        acc3 = __fadd_rn(acc3, p3);

        // Epilogue: I = ff + rec (single RN add), v = 0.9*v + I UNCONTRACTED.
        float I0 = __fadd_rn(ff.x, acc0);
        float I1 = __fadd_rn(ff.y, acc1);
        float I2 = __fadd_rn(ff.z, acc2);
        float I3 = __fadd_rn(ff.w, acc3);
        v.x = __fadd_rn(__fmul_rn(DECAY, v.x), I0);
        v.y = __fadd_rn(__fmul_rn(DECAY, v.y), I1);
        v.z = __fadd_rn(__fmul_rn(DECAY, v.z), I2);
        v.w = __fadd_rn(__fmul_rn(DECAY, v.w), I3);
        unsigned b0 = (v.x >= VTH) ? 1u : 0u;
        unsigned b1 = (v.y >= VTH) ? 1u : 0u;
        unsigned b2 = (v.z >= VTH) ? 1u : 0u;
        unsigned b3 = (v.w >= VTH) ? 1u : 0u;
        if (b0) v.x = 0.0f;
        if (b1) v.y = 0.0f;
        if (b2) v.z = 0.0f;
        if (b3) v.w = 0.0f;
        *(float4*)(g_vr + off) = v;

        // reservoir_spikes_accum (integer-valued fp adds; exact)
        float4* ac = (float4*)(d_out + NCLS * BB + off);
        float4 a = *ac;
        a.x += (float)b0; a.y += (float)b1; a.z += (float)b2; a.w += (float)b3;
        *ac = a;

        // Publish spike mask for s_step.
        unsigned nib = b0 | (b1 << 1) | (b2 << 2) | (b3 << 3);
        atomicOr(&msk[b], nib << jb);
        __syncthreads();
        if (tid < 64) g_mask[wb][tid * NRES_BLOCKS + bid] = msk[tid];
    } else {
        // Classifier for s_{step-1}: serial ascending-k adds over spike list
        // (bit-identical to the confirmed serial fmaf chain).
        if (step == 0) return;
        int idx = (bid - NRES_BLOCKS) * THREADS + tid;
        if (idx >= BB * NCLS) return;
        int b   = idx / NCLS;
        int cls = idx % NCLS;
        const unsigned* mrow = &g_mask[rb][b * NRES_BLOCKS];
        const float* wr = Wclf + (size_t)cls * NRES;
        float acc = 0.f;
        for (int i = 0; i < NRES_BLOCKS; i++) {
            unsigned m = mrow[i];
            while (m) {
                unsigned t = m & (0u - m);
                int k = (i << 4) + __popc(t - 1u);
                m ^= t;
                acc = __fadd_rn(acc, wr[k]);
            }
        }
        float vc = g_vc[idx];
        vc = __fadd_rn(__fmul_rn(DECAY, vc), acc);
        if (vc >= VTH) {
            d_out[idx] += 1.0f;
            vc = 0.0f;
        }
        g_vc[idx] = vc;
    }
}

// ---------------------------------------------------------------------------
extern "C" void kernel_launch(void* const* d_in, const int* in_sizes, int n_in,
                              void* d_out, int out_size) {
    const float* x    = (const float*)d_in[0];  // (64,128,500)
    const float* Win  = (const float*)d_in[1];  // (2048,128)
    const float* Wres = (const float*)d_in[2];  // (2048,2048)
    const float* Wclf = (const float*)d_in[3];  // (10,2048)
    float* out = (float*)d_out;                 // [640 counts | 131072 accum]

    cudaFuncSetAttribute(step_kernel,
                         cudaFuncAttributeMaxDynamicSharedMemorySize, SMEM_BYTES);

    {
        int n = BB * NRES;
        if (out_size > n) n = out_size;
        int grid = (n + THREADS - 1) / THREADS;
        zero_init_kernel<<<grid, THREADS>>>(out, out_size);
    }

    transpose_win_kernel<<<(CC * NRES + THREADS - 1) / THREADS, THREADS>>>(Win);
    build_wslice_kernel<<<dim3(NRES / 32, NRES / 32), dim3(32, 8)>>>(Wres);

    // Precompute all feedforward drives FF[t][b][j]
    ff_kernel<<<TT * BB, 256>>>(x);

    // Sequential LIF steps; step==TT runs only the final classifier.
    for (int t = 0; t <= TT; t++) {
        step_kernel<<<NRES_BLOCKS + CLF_BLOCKS, THREADS, SMEM_BYTES>>>(
            t, Wclf, out);
    }
}